// round 1
// baseline (speedup 1.0000x reference)
#include <cuda_runtime.h>

#define IN_DIM   256
#define OUT_DIM  256
#define N_KNOTS  9
#define NB       5          // N_BASIS
#define B_TILE   16         // batch rows per block
#define THREADS  256
#define SMEM_BYTES (IN_DIM * B_TILE * NB * 4)   // 80 KB

__global__ __launch_bounds__(THREADS, 2)
void kan_kernel(const float* __restrict__ x,
                const float* __restrict__ grids,
                const float* __restrict__ coef,
                float* __restrict__ y,
                float* __restrict__ acts)
{
    extern __shared__ float sbasis[];   // [IN_DIM][B_TILE][NB]
    const int t  = threadIdx.x;
    const int b0 = blockIdx.x * B_TILE;

    // ---------------- Phase 1: B-spline basis for i = t, all 16 rows ----------
    {
        const int i = t;
        float tk[N_KNOTS];
        #pragma unroll
        for (int k = 0; k < N_KNOTS; k++) tk[k] = grids[i * N_KNOTS + k];

        // reciprocal knot-difference denominators (depend only on i, not row)
        float iL1[7], iR1[7], iL2[6], iR2[6], iL3[5], iR3[5];
        #pragma unroll
        for (int j = 0; j < 7; j++) { iL1[j] = 1.f / (tk[j+1] - tk[j]); iR1[j] = 1.f / (tk[j+2] - tk[j+1]); }
        #pragma unroll
        for (int j = 0; j < 6; j++) { iL2[j] = 1.f / (tk[j+2] - tk[j]); iR2[j] = 1.f / (tk[j+3] - tk[j+1]); }
        #pragma unroll
        for (int j = 0; j < 5; j++) { iL3[j] = 1.f / (tk[j+3] - tk[j]); iR3[j] = 1.f / (tk[j+4] - tk[j+1]); }

        for (int r = 0; r < B_TILE; r++) {
            const float xv = x[(size_t)(b0 + r) * IN_DIM + i];
            float bas[8];
            #pragma unroll
            for (int j = 0; j < 8; j++)
                bas[j] = (xv >= tk[j] && xv < tk[j+1]) ? 1.0f : 0.0f;
            #pragma unroll
            for (int j = 0; j < 7; j++)
                bas[j] = (xv - tk[j]) * iL1[j] * bas[j] + (tk[j+2] - xv) * iR1[j] * bas[j+1];
            #pragma unroll
            for (int j = 0; j < 6; j++)
                bas[j] = (xv - tk[j]) * iL2[j] * bas[j] + (tk[j+3] - xv) * iR2[j] * bas[j+1];
            #pragma unroll
            for (int j = 0; j < 5; j++)
                bas[j] = (xv - tk[j]) * iL3[j] * bas[j] + (tk[j+4] - xv) * iR3[j] * bas[j+1];

            float* sp = &sbasis[(i * B_TILE + r) * NB];
            #pragma unroll
            for (int n = 0; n < NB; n++) sp[n] = bas[n];
        }
    }
    __syncthreads();

    // ---------------- Phase 2: acts + y ---------------------------------------
    // thread -> 4 consecutive output cols (o4..o4+3) x 4 rows (rg4..rg4+3)
    const int og  = t & 63;
    const int o4  = og * 4;
    const int rg4 = (t >> 6) * 4;

    float4 acc[4];
    #pragma unroll
    for (int r = 0; r < 4; r++) acc[r] = make_float4(0.f, 0.f, 0.f, 0.f);

    const float* cbase = coef + (size_t)o4 * NB;   // coef[i][o4][0]
    float4 c0, c1, c2, c3, c4;
    {
        const float4* cp = reinterpret_cast<const float4*>(cbase);
        c0 = cp[0]; c1 = cp[1]; c2 = cp[2]; c3 = cp[3]; c4 = cp[4];
    }

    float* actp = acts + (size_t)(b0 + rg4) * (IN_DIM * OUT_DIM) + o4;

    for (int i = 0; i < IN_DIM; i++) {
        // prefetch next coeff row
        float4 n0, n1, n2, n3, n4;
        if (i + 1 < IN_DIM) {
            const float4* cp = reinterpret_cast<const float4*>(
                cbase + (size_t)(i + 1) * (OUT_DIM * NB));
            n0 = cp[0]; n1 = cp[1]; n2 = cp[2]; n3 = cp[3]; n4 = cp[4];
        }

        // unpack 4 output cols x 5 basis coeffs
        const float cf[4][5] = {
            { c0.x, c0.y, c0.z, c0.w, c1.x },
            { c1.y, c1.z, c1.w, c2.x, c2.y },
            { c2.z, c2.w, c3.x, c3.y, c3.z },
            { c3.w, c4.x, c4.y, c4.z, c4.w }
        };

        const float* bp = &sbasis[(i * B_TILE + rg4) * NB];
        #pragma unroll
        for (int r = 0; r < 4; r++) {
            const float bb0 = bp[r*NB+0], bb1 = bp[r*NB+1], bb2 = bp[r*NB+2],
                        bb3 = bp[r*NB+3], bb4 = bp[r*NB+4];
            float4 v;
            v.x = bb0*cf[0][0] + bb1*cf[0][1] + bb2*cf[0][2] + bb3*cf[0][3] + bb4*cf[0][4];
            v.y = bb0*cf[1][0] + bb1*cf[1][1] + bb2*cf[1][2] + bb3*cf[1][3] + bb4*cf[1][4];
            v.z = bb0*cf[2][0] + bb1*cf[2][1] + bb2*cf[2][2] + bb3*cf[2][3] + bb4*cf[2][4];
            v.w = bb0*cf[3][0] + bb1*cf[3][1] + bb2*cf[3][2] + bb3*cf[3][3] + bb4*cf[3][4];

            *reinterpret_cast<float4*>(actp + (size_t)r * (IN_DIM * OUT_DIM) + i * OUT_DIM) = v;

            acc[r].x += v.x; acc[r].y += v.y; acc[r].z += v.z; acc[r].w += v.w;
        }

        c0 = n0; c1 = n1; c2 = n2; c3 = n3; c4 = n4;
    }

    // y = sum over i (this block owns ALL i for its rows -> single write)
    float* yp = y + (size_t)(b0 + rg4) * OUT_DIM + o4;
    #pragma unroll
    for (int r = 0; r < 4; r++)
        *reinterpret_cast<float4*>(yp + (size_t)r * OUT_DIM) = acc[r];
}

extern "C" void kernel_launch(void* const* d_in, const int* in_sizes, int n_in,
                              void* d_out, int out_size)
{
    const float* x     = (const float*)d_in[0];
    const float* grids = (const float*)d_in[1];
    const float* coef  = (const float*)d_in[2];

    const int B = in_sizes[0] / IN_DIM;   // 4096

    float* y    = (float*)d_out;                          // (B, OUT_DIM) first
    float* acts = (float*)d_out + (size_t)B * OUT_DIM;    // (B, IN_DIM, OUT_DIM) second

    cudaFuncSetAttribute(kan_kernel,
                         cudaFuncAttributeMaxDynamicSharedMemorySize, SMEM_BYTES);
    kan_kernel<<<B / B_TILE, THREADS, SMEM_BYTES>>>(x, grids, coef, y, acts);
}